// round 6
// baseline (speedup 1.0000x reference)
#include <cuda_runtime.h>
#include <cuda_bf16.h>
#include <cstdint>

// LoRA fused single-kernel (round 5):
//   per block (32 m rows): t[m][r] = sum_k x[m][k] * At[k][r]   (full k)
//   then in-block:          out[m][o] = sum_r t[m][r]*B[o][r] + bias[o]
// prep kernel builds At[k][r] = 2*A[r][k] once.

#define IN_F   4096
#define OUT_F  4096
#define RANK   16
#define M_TOT  8192

#define MT     32          // m rows per block
#define THR    256
#define KC     64          // k chunk staged in smem
#define NCH    (IN_F / KC) // 64
#define XP     33          // xs row pitch (floats)

__device__ __align__(16) float g_At[IN_F * RANK];   // 256 KB, k-major, x2 folded

typedef unsigned long long u64;

__device__ __forceinline__ u64 pk2(float lo, float hi) {
    u64 r; asm("mov.b64 %0, {%1,%2};" : "=l"(r) : "f"(lo), "f"(hi)); return r;
}
__device__ __forceinline__ void fma2(u64 &d, u64 a, u64 b) {
    asm("fma.rn.f32x2 %0, %1, %2, %0;" : "+l"(d) : "l"(a), "l"(b));
}
__device__ __forceinline__ float2 up2(u64 v) {
    float2 f; asm("mov.b64 {%0,%1}, %2;" : "=f"(f.x), "=f"(f.y) : "l"(v)); return f;
}

// ---------------- prep: At = 2 * A^T (coalesced reads) ----------------
__global__ void prep_At(const float* __restrict__ A) {
    const int i  = blockIdx.x * 256 + threadIdx.x;   // 16384 threads
    const int r  = i >> 10;
    const int k4 = i & 1023;
    const float4 v = *(const float4*)&A[r * IN_F + k4 * 4];
    const int k = 4 * k4;
    g_At[(k + 0) * RANK + r] = 2.0f * v.x;
    g_At[(k + 1) * RANK + r] = 2.0f * v.y;
    g_At[(k + 2) * RANK + r] = 2.0f * v.z;
    g_At[(k + 3) * RANK + r] = 2.0f * v.w;
}

// ---------------- fused kernel ----------------
// smem map (29184 B total):
//   [0      , 16896)  xs[2][KC][XP]        (phase-1 x tiles)
//   [16896  , 25088)  as4[2][KC*4] float4  (phase-1 At tiles)
//   [0      , 18432)  red[8][32][9] u64    (aliases xs/as after k-loop)
//   [25088  , 29184)  t_d[32][16] u64      (duplicated t for phase 2)
__global__ __launch_bounds__(THR, 4)
void lora_fused(const float* __restrict__ x,
                const float* __restrict__ B,
                const float* __restrict__ bias,
                float* __restrict__ out)
{
    __shared__ __align__(16) char smem_raw[29184];
    float*  xs  = (float*)smem_raw;                    // [2][KC][XP]
    float4* as4 = (float4*)(smem_raw + 16896);         // [2][KC*4]
    u64*    red = (u64*)smem_raw;                      // [8][32][9]
    u64*    t_d = (u64*)(smem_raw + 25088);            // [32][16]

    const int tid  = threadIdx.x;
    const int lane = tid & 31;
    const int w    = tid >> 5;                 // 8 warps
    const int mbase = blockIdx.x * MT;

    // staging geometry: thread -> (m row sm, k-octet sk)
    const int sm = tid >> 3;                   // 0..31
    const int sk = tid & 7;                    // 0..7
    const float* xrow = x + (size_t)(mbase + sm) * IN_F;

    // rank-pair accumulators, lane <-> m
    u64 acc[8];
    #pragma unroll
    for (int rp = 0; rp < 8; ++rp) acc[rp] = 0ull;

    float4 xr0, xr1, ar;

    // prologue: chunk 0
    xr0 = *(const float4*)(xrow + sk * 8);
    xr1 = *(const float4*)(xrow + sk * 8 + 4);
    ar  = ((const float4*)g_At)[tid];

    {
        float* xb = xs;                        // buf 0
        xb[(sk * 8 + 0) * XP + sm] = xr0.x;
        xb[(sk * 8 + 1) * XP + sm] = xr0.y;
        xb[(sk * 8 + 2) * XP + sm] = xr0.z;
        xb[(sk * 8 + 3) * XP + sm] = xr0.w;
        xb[(sk * 8 + 4) * XP + sm] = xr1.x;
        xb[(sk * 8 + 5) * XP + sm] = xr1.y;
        xb[(sk * 8 + 6) * XP + sm] = xr1.z;
        xb[(sk * 8 + 7) * XP + sm] = xr1.w;
        as4[tid] = ar;
    }
    __syncthreads();

    for (int c = 0; c < NCH; ++c) {
        const int buf = c & 1;

        if (c + 1 < NCH) {                     // prefetch next chunk
            const int kc1 = (c + 1) * KC;
            xr0 = *(const float4*)(xrow + kc1 + sk * 8);
            xr1 = *(const float4*)(xrow + kc1 + sk * 8 + 4);
            ar  = ((const float4*)g_At)[kc1 * 4 + tid];
        }

        // compute: warp w covers k = w*8 .. w*8+7 of this chunk
        const float*  xbase = xs + buf * (KC * XP);
        const float4* abase = as4 + buf * (KC * 4);
        #pragma unroll
        for (int kk = 0; kk < 8; ++kk) {
            const int k = w * 8 + kk;
            const float xv = xbase[k * XP + lane];      // x[m=lane][k]
            const u64 xd = pk2(xv, xv);
            const ulonglong2* ap = (const ulonglong2*)(abase + k * 4);
            const ulonglong2 a01 = ap[0], a23 = ap[1];
            fma2(acc[0], xd, a01.x);
            fma2(acc[1], xd, a01.y);
            fma2(acc[2], xd, a23.x);
            fma2(acc[3], xd, a23.y);
            const ulonglong2 a45 = ap[2], a67 = ap[3];
            fma2(acc[4], xd, a45.x);
            fma2(acc[5], xd, a45.y);
            fma2(acc[6], xd, a67.x);
            fma2(acc[7], xd, a67.y);
        }

        if (c + 1 < NCH) {
            float* xb = xs + ((c + 1) & 1) * (KC * XP);
            xb[(sk * 8 + 0) * XP + sm] = xr0.x;
            xb[(sk * 8 + 1) * XP + sm] = xr0.y;
            xb[(sk * 8 + 2) * XP + sm] = xr0.z;
            xb[(sk * 8 + 3) * XP + sm] = xr0.w;
            xb[(sk * 8 + 4) * XP + sm] = xr1.x;
            xb[(sk * 8 + 5) * XP + sm] = xr1.y;
            xb[(sk * 8 + 6) * XP + sm] = xr1.z;
            xb[(sk * 8 + 7) * XP + sm] = xr1.w;
            as4[((c + 1) & 1) * 256 + tid] = ar;
        }
        __syncthreads();
    }

    // ---- cross-warp reduction: red aliases xs/as, all reads done ----
    #pragma unroll
    for (int rp = 0; rp < 8; ++rp)
        red[(w * 32 + lane) * 9 + rp] = acc[rp];
    __syncthreads();

    {   // thread t: m = t>>3, rank-pair rp = t&7
        const int m  = tid >> 3;
        const int rp = tid & 7;
        float2 s = make_float2(0.f, 0.f);
        #pragma unroll
        for (int w8 = 0; w8 < 8; ++w8) {
            const float2 f = up2(red[(w8 * 32 + m) * 9 + rp]);
            s.x += f.x; s.y += f.y;
        }
        t_d[m * 16 + 2 * rp]     = pk2(s.x, s.x);
        t_d[m * 16 + 2 * rp + 1] = pk2(s.y, s.y);
    }
    __syncthreads();

    // ---------------- phase 2 (in-block) ----------------
    // thread owns 2 o-columns per chunk; 8 chunks cover OUT_F.
    for (int oc = 0; oc < 8; ++oc) {
        const int o0 = oc * 512 + tid * 2;

        // load 2 B rows once, pack o-pairs
        float B0[RANK], B1[RANK];
        #pragma unroll
        for (int q = 0; q < 4; ++q) {
            *(float4*)&B0[4 * q] = *(const float4*)&B[(size_t)(o0)     * RANK + 4 * q];
            *(float4*)&B1[4 * q] = *(const float4*)&B[(size_t)(o0 + 1) * RANK + 4 * q];
        }
        u64 bu[RANK];
        #pragma unroll
        for (int r = 0; r < RANK; ++r) bu[r] = pk2(B0[r], B1[r]);

        const float2 bi = *(const float2*)&bias[o0];
        const u64 bias2 = pk2(bi.x, bi.y);

        #pragma unroll 4
        for (int m = 0; m < MT; ++m) {
            const ulonglong2* tp = (const ulonglong2*)(t_d + m * 16);
            u64 a = bias2;
            #pragma unroll
            for (int rp = 0; rp < 8; ++rp) {
                const ulonglong2 t2 = tp[rp];
                fma2(a, t2.x, bu[2 * rp]);
                fma2(a, t2.y, bu[2 * rp + 1]);
            }
            const float2 f = up2(a);
            *(float2*)&out[(size_t)(mbase + m) * OUT_F + o0] = f;
        }
    }
}

extern "C" void kernel_launch(void* const* d_in, const int* in_sizes, int n_in,
                              void* d_out, int out_size) {
    const float* x    = (const float*)d_in[0];   // [8192, 4096]
    const float* A    = (const float*)d_in[1];   // [16, 4096]
    const float* B    = (const float*)d_in[2];   // [4096, 16]
    const float* bias = (const float*)d_in[3];   // [4096]
    float* out = (float*)d_out;                  // [8192, 4096]

    prep_At<<<64, 256>>>(A);
    lora_fused<<<M_TOT / MT, THR>>>(x, B, bias, out);
}

// round 7
// speedup vs baseline: 1.0768x; 1.0768x over previous
#include <cuda_runtime.h>
#include <cuda_bf16.h>
#include <cstdint>

// LoRA low-rank, 3-kernel pipeline (round 6):
//   prep   : At[k][r] = 2 * A[r][k]
//   phase1 : tp[ks][m][r] = sum_{k in slice} x[m][k] * At[k][r]
//            (full-line LDG mapping, conflict-free transpose, 4 m/lane)
//   phase2 : out[m][o] = sum_r (sum_ks tp) * B[o][r] + bias[o]   (R4 design)

#define IN_F   4096
#define OUT_F  4096
#define RANK   16
#define M_TOT  8192

#define KSPLIT 8
#define KRANGE (IN_F / KSPLIT)    // 512
#define MT     128                // m rows per phase-1 block
#define KC     32                 // k chunk staged in smem
#define NCH    (KRANGE / KC)      // 16
#define XP     129                // xs pitch (floats): conflict-free transpose

#define OTPB   1024               // o columns per phase-2 block
#define MSLAB  128                // m rows per phase-2 block

__device__ __align__(16) float g_At[IN_F * RANK];            // 256 KB
__device__ __align__(16) float g_tp[KSPLIT][M_TOT][RANK];    // 4 MB partials

typedef unsigned long long u64;

__device__ __forceinline__ u64 pk2(float lo, float hi) {
    u64 r; asm("mov.b64 %0, {%1,%2};" : "=l"(r) : "f"(lo), "f"(hi)); return r;
}
__device__ __forceinline__ void fma2(u64 &d, u64 a, u64 b) {
    asm("fma.rn.f32x2 %0, %1, %2, %0;" : "+l"(d) : "l"(a), "l"(b));
}
__device__ __forceinline__ float2 up2(u64 v) {
    float2 f; asm("mov.b64 {%0,%1}, %2;" : "=f"(f.x), "=f"(f.y) : "l"(v)); return f;
}

// ---------------- prep: At = 2*A^T, coalesced STG.128 ----------------
__global__ void prep_At(const float* __restrict__ A) {
    const int i  = blockIdx.x * 256 + threadIdx.x;   // 16384
    const int k  = i >> 2;
    const int rq = i & 3;
    float4 v;
    v.x = 2.0f * A[(size_t)(4 * rq + 0) * IN_F + k];
    v.y = 2.0f * A[(size_t)(4 * rq + 1) * IN_F + k];
    v.z = 2.0f * A[(size_t)(4 * rq + 2) * IN_F + k];
    v.w = 2.0f * A[(size_t)(4 * rq + 3) * IN_F + k];
    ((float4*)g_At)[k * 4 + rq] = v;
}

// ---------------- phase 1 ----------------
// smem: [0,33024) xs[2][KC][XP] floats ; [33024,37120) as4[2][KC*4] float4
//       red[4][MT][9] u64 (36864 B) aliases the whole block after k-loop.
__global__ __launch_bounds__(256, 2)
void lora_phase1(const float* __restrict__ x) {
    __shared__ __align__(16) char sraw[37120];
    float*  xs  = (float*)sraw;
    float4* as4 = (float4*)(sraw + 33024);
    u64*    red = (u64*)sraw;

    const int tid  = threadIdx.x;
    const int lane = tid & 31;
    const int w    = tid >> 5;                  // 8 warps
    const int ks   = blockIdx.x & (KSPLIT - 1);
    const int mt   = blockIdx.x >> 3;           // 0..63
    const int mbase = mt * MT;
    const int k0    = ks * KRANGE;

    // LDG mapping: lanes 0..7 cover one full 128B line of one row.
    const int lm = tid >> 3;                    // row within 32-row group
    const int lc = (tid & 7) * 4;               // col (floats) within chunk
    const float* xg = x + (size_t)(mbase + lm) * IN_F + k0 + lc;

    u64 acc[4][8];
    #pragma unroll
    for (int mm = 0; mm < 4; ++mm)
        #pragma unroll
        for (int rp = 0; rp < 8; ++rp) acc[mm][rp] = 0ull;

    float4 xr[4], ar;

    // prologue: chunk 0
    #pragma unroll
    for (int i = 0; i < 4; ++i)
        xr[i] = *(const float4*)(xg + (size_t)(32 * i) * IN_F);
    if (tid < 128) ar = ((const float4*)g_At)[k0 * 4 + tid];

    #pragma unroll
    for (int i = 0; i < 4; ++i) {
        float* xb = xs;                         // buf 0
        const int m = 32 * i + lm;
        xb[(lc + 0) * XP + m] = xr[i].x;
        xb[(lc + 1) * XP + m] = xr[i].y;
        xb[(lc + 2) * XP + m] = xr[i].z;
        xb[(lc + 3) * XP + m] = xr[i].w;
    }
    if (tid < 128) as4[tid] = ar;
    __syncthreads();

    for (int c = 0; c < NCH; ++c) {
        const int buf = c & 1;

        if (c + 1 < NCH) {                      // prefetch chunk c+1
            const int kc1 = (c + 1) * KC;
            #pragma unroll
            for (int i = 0; i < 4; ++i)
                xr[i] = *(const float4*)(xg + kc1 + (size_t)(32 * i) * IN_F);
            if (tid < 128) ar = ((const float4*)g_At)[(k0 + kc1) * 4 + tid];
        }

        // compute: warp w covers k = w*4 .. w*4+3 of this chunk
        const float*  xbc = xs + buf * (KC * XP);
        const float4* abc = as4 + buf * (KC * 4);
        #pragma unroll
        for (int kk = 0; kk < 4; ++kk) {
            const int k = w * 4 + kk;
            u64 xd[4];
            #pragma unroll
            for (int mm = 0; mm < 4; ++mm) {
                const float xv = xbc[k * XP + lane + 32 * mm];
                xd[mm] = pk2(xv, xv);
            }
            const ulonglong2* ap = (const ulonglong2*)(abc + k * 4);
            const ulonglong2 a01 = ap[0], a23 = ap[1];
            #pragma unroll
            for (int mm = 0; mm < 4; ++mm) {
                fma2(acc[mm][0], xd[mm], a01.x);
                fma2(acc[mm][1], xd[mm], a01.y);
                fma2(acc[mm][2], xd[mm], a23.x);
                fma2(acc[mm][3], xd[mm], a23.y);
            }
            const ulonglong2 a45 = ap[2], a67 = ap[3];
            #pragma unroll
            for (int mm = 0; mm < 4; ++mm) {
                fma2(acc[mm][4], xd[mm], a45.x);
                fma2(acc[mm][5], xd[mm], a45.y);
                fma2(acc[mm][6], xd[mm], a67.x);
                fma2(acc[mm][7], xd[mm], a67.y);
            }
        }

        if (c + 1 < NCH) {                      // stage chunk c+1
            float* xb = xs + ((c + 1) & 1) * (KC * XP);
            #pragma unroll
            for (int i = 0; i < 4; ++i) {
                const int m = 32 * i + lm;
                xb[(lc + 0) * XP + m] = xr[i].x;
                xb[(lc + 1) * XP + m] = xr[i].y;
                xb[(lc + 2) * XP + m] = xr[i].z;
                xb[(lc + 3) * XP + m] = xr[i].w;
            }
            if (tid < 128) as4[((c + 1) & 1) * (KC * 4) + tid] = ar;
        }
        __syncthreads();
    }

    // ---- two-pass cross-warp reduction (red aliases xs/as4) ----
    if (w < 4) {
        #pragma unroll
        for (int mm = 0; mm < 4; ++mm) {
            const int m = lane + 32 * mm;
            #pragma unroll
            for (int rp = 0; rp < 8; ++rp)
                red[w * 1152 + m * 9 + rp] = acc[mm][rp];
        }
    }
    __syncthreads();
    if (w >= 4) {
        const int w2 = w - 4;
        #pragma unroll
        for (int mm = 0; mm < 4; ++mm) {
            const int m = lane + 32 * mm;
            #pragma unroll
            for (int rp = 0; rp < 8; ++rp) {
                const float2 a = up2(red[w2 * 1152 + m * 9 + rp]);
                const float2 b = up2(acc[mm][rp]);
                red[w2 * 1152 + m * 9 + rp] = pk2(a.x + b.x, a.y + b.y);
            }
        }
    }
    __syncthreads();

    {   // final: thread -> (m = tid>>1, rank half h = tid&1)
        const int m = tid >> 1;
        const int h = tid & 1;
        float o[8];
        #pragma unroll
        for (int rp = 0; rp < 4; ++rp) {
            const int rr = h * 4 + rp;
            float sx = 0.f, sy = 0.f;
            #pragma unroll
            for (int w4 = 0; w4 < 4; ++w4) {
                const float2 f = up2(red[w4 * 1152 + m * 9 + rr]);
                sx += f.x; sy += f.y;
            }
            o[2 * rp]     = sx;
            o[2 * rp + 1] = sy;
        }
        float* dst = &g_tp[ks][mbase + m][8 * h];
        *(float4*)(dst)     = make_float4(o[0], o[1], o[2], o[3]);
        *(float4*)(dst + 4) = make_float4(o[4], o[5], o[6], o[7]);
    }
}

// ---------------- phase 2 (R4 design, unchanged) ----------------
__global__ __launch_bounds__(256, 2)
void lora_phase2(const float* __restrict__ B,
                 const float* __restrict__ bias,
                 float* __restrict__ out) {
    __shared__ u64 t_d[MSLAB][RANK];     // 16 KB, (t,t) duplicated

    const int tid   = threadIdx.x;
    const int oblk  = blockIdx.x & 3;
    const int mslab = blockIdx.x >> 2;
    const int o0    = oblk * OTPB + tid * 4;
    const int m0    = mslab * MSLAB;

    u64 bu[2][RANK];
    #pragma unroll
    for (int op = 0; op < 2; ++op) {
        float Bv0[RANK], Bv1[RANK];
        #pragma unroll
        for (int q = 0; q < 4; ++q) {
            *(float4*)&Bv0[4 * q] = *(const float4*)&B[(size_t)(o0 + 2 * op)     * RANK + 4 * q];
            *(float4*)&Bv1[4 * q] = *(const float4*)&B[(size_t)(o0 + 2 * op + 1) * RANK + 4 * q];
        }
        #pragma unroll
        for (int r = 0; r < RANK; ++r)
            bu[op][r] = pk2(Bv0[r], Bv1[r]);
    }
    const float4 bi4 = *(const float4*)&bias[o0];
    const u64 bias2[2] = { pk2(bi4.x, bi4.y), pk2(bi4.z, bi4.w) };

    #pragma unroll
    for (int j = 0; j < 2; ++j) {
        const int idx = tid * 2 + j;      // 0..511
        const int m = idx >> 2, q = idx & 3;
        float4 s = make_float4(0, 0, 0, 0);
        #pragma unroll
        for (int sl = 0; sl < KSPLIT; ++sl) {
            const float4 v = *(const float4*)&g_tp[sl][m0 + m][4 * q];
            s.x += v.x; s.y += v.y; s.z += v.z; s.w += v.w;
        }
        t_d[m][4 * q + 0] = pk2(s.x, s.x);
        t_d[m][4 * q + 1] = pk2(s.y, s.y);
        t_d[m][4 * q + 2] = pk2(s.z, s.z);
        t_d[m][4 * q + 3] = pk2(s.w, s.w);
    }
    __syncthreads();

    for (int m = 0; m < MSLAB; ++m) {
        const ulonglong2* tp = (const ulonglong2*)&t_d[m][0];
        u64 a0 = bias2[0], a1 = bias2[1];
        #pragma unroll
        for (int rp = 0; rp < 8; ++rp) {
            const ulonglong2 t2 = tp[rp];
            fma2(a0, t2.x, bu[0][2 * rp]);
            fma2(a1, t2.x, bu[1][2 * rp]);
            fma2(a0, t2.y, bu[0][2 * rp + 1]);
            fma2(a1, t2.y, bu[1][2 * rp + 1]);
        }
        const float2 lo = up2(a0), hi = up2(a1);
        *(float4*)&out[(size_t)(m0 + m) * OUT_F + o0] =
            make_float4(lo.x, lo.y, hi.x, hi.y);
    }
}

extern "C" void kernel_launch(void* const* d_in, const int* in_sizes, int n_in,
                              void* d_out, int out_size) {
    const float* x    = (const float*)d_in[0];   // [8192, 4096]
    const float* A    = (const float*)d_in[1];   // [16, 4096]
    const float* B    = (const float*)d_in[2];   // [4096, 16]
    const float* bias = (const float*)d_in[3];   // [4096]
    float* out = (float*)d_out;                  // [8192, 4096]

    prep_At<<<64, 256>>>(A);
    lora_phase1<<<(M_TOT / MT) * KSPLIT, 256>>>(x);
    lora_phase2<<<(OUT_F / OTPB) * (M_TOT / MSLAB), 256>>>(B, bias, out);
}